// round 1
// baseline (speedup 1.0000x reference)
#include <cuda_runtime.h>
#include <math.h>

#define BDIM 2048
#define D 1024
#define C 8192
#define NB (C / 128)   // 64 column blocks

// ---------------- scratch (device globals; no allocations) ----------------
__device__ float g_c2[C];
__device__ float g_pmax[BDIM * NB];
__device__ int   g_pidx[BDIM * NB];
__device__ float g_psum[BDIM * NB];
__device__ float g_sy[BDIM];
__device__ float g_rloss[BDIM];
__device__ float g_rmatch[BDIM];

// ---------------- kernel 1: c2[c] = sum_k centroids[c,k]^2 ----------------
__global__ void c2_kernel(const float* __restrict__ cent) {
    int c = blockIdx.x;
    const float4* row = (const float4*)(cent + (size_t)c * D);
    float4 v = row[threadIdx.x];          // 256 threads * 4 = 1024 elems
    float s = v.x * v.x + v.y * v.y + v.z * v.z + v.w * v.w;
    __shared__ float sh[8];
    #pragma unroll
    for (int o = 16; o > 0; o >>= 1) s += __shfl_down_sync(0xffffffffu, s, o);
    if ((threadIdx.x & 31) == 0) sh[threadIdx.x >> 5] = s;
    __syncthreads();
    if (threadIdx.x < 8) {
        s = sh[threadIdx.x];
        #pragma unroll
        for (int o = 4; o > 0; o >>= 1) s += __shfl_down_sync(0xffu, s, o);
        if (threadIdx.x == 0) g_c2[c] = s;
    }
}

// ---------------- kernel 2: fused GEMM + per-block softmax partials -------
// s[b,c] = 2*(x.c) - c2[c].  Block tile 128x128, BK=16, 256 threads, 8x8/thread.
#define BK 16

__global__ __launch_bounds__(256, 2) void gemm_kernel(
    const float* __restrict__ x, const int* __restrict__ y,
    const float* __restrict__ cent)
{
    __shared__ float As[BK][128];
    __shared__ float Bs[BK][128];
    __shared__ float redv[128][16];
    __shared__ int   redi[128][16];
    __shared__ float rowmax[128];
    __shared__ float c2s[128];

    const int nb = blockIdx.x;         // centroid block
    const int mb = blockIdx.y;         // batch block
    const int tid = threadIdx.x;
    const int tx = tid & 15;
    const int ty = tid >> 4;

    if (tid < 128) c2s[tid] = g_c2[nb * 128 + tid];

    const float* Ab = x    + (size_t)mb * 128 * D;
    const float* Bb = cent + (size_t)nb * 128 * D;

    float acc[8][8];
    #pragma unroll
    for (int i = 0; i < 8; i++)
        #pragma unroll
        for (int j = 0; j < 8; j++) acc[i][j] = 0.f;

    const int lr = tid >> 2;          // 0..63
    const int lk = (tid & 3) * 4;     // 0,4,8,12

    for (int kt = 0; kt < D; kt += BK) {
        #pragma unroll
        for (int h = 0; h < 2; h++) {
            int row = lr + h * 64;
            float4 av = *(const float4*)(Ab + (size_t)row * D + kt + lk);
            As[lk + 0][row] = av.x; As[lk + 1][row] = av.y;
            As[lk + 2][row] = av.z; As[lk + 3][row] = av.w;
            float4 bv = *(const float4*)(Bb + (size_t)row * D + kt + lk);
            Bs[lk + 0][row] = bv.x; Bs[lk + 1][row] = bv.y;
            Bs[lk + 2][row] = bv.z; Bs[lk + 3][row] = bv.w;
        }
        __syncthreads();
        #pragma unroll
        for (int kk = 0; kk < BK; kk++) {
            float a[8], b[8];
            float4 a0 = *(const float4*)&As[kk][ty * 8];
            float4 a1 = *(const float4*)&As[kk][ty * 8 + 4];
            float4 b0 = *(const float4*)&Bs[kk][tx * 8];
            float4 b1 = *(const float4*)&Bs[kk][tx * 8 + 4];
            a[0]=a0.x; a[1]=a0.y; a[2]=a0.z; a[3]=a0.w;
            a[4]=a1.x; a[5]=a1.y; a[6]=a1.z; a[7]=a1.w;
            b[0]=b0.x; b[1]=b0.y; b[2]=b0.z; b[3]=b0.w;
            b[4]=b1.x; b[5]=b1.y; b[6]=b1.z; b[7]=b1.w;
            #pragma unroll
            for (int i = 0; i < 8; i++)
                #pragma unroll
                for (int j = 0; j < 8; j++)
                    acc[i][j] = fmaf(a[i], b[j], acc[i][j]);
        }
        __syncthreads();
    }

    // ---- epilogue: s = 2*acc - c2; per-row (block-local) max/argmax ----
    int yv[8];
    #pragma unroll
    for (int i = 0; i < 8; i++) yv[i] = y[mb * 128 + ty * 8 + i];

    #pragma unroll
    for (int i = 0; i < 8; i++) {
        float m = -INFINITY; int mi = 0;
        #pragma unroll
        for (int j = 0; j < 8; j++) {
            int cl = tx * 8 + j;
            float s = 2.f * acc[i][j] - c2s[cl];
            acc[i][j] = s;
            if (s > m) { m = s; mi = cl; }
            if (nb * 128 + cl == yv[i]) g_sy[mb * 128 + ty * 8 + i] = s;
        }
        redv[ty * 8 + i][tx] = m;
        redi[ty * 8 + i][tx] = mi;
    }
    __syncthreads();
    if (tid < 128) {
        float m = -INFINITY; int mi = 0x7fffffff;
        #pragma unroll
        for (int t = 0; t < 16; t++) {
            float v = redv[tid][t]; int ix = redi[tid][t];
            if (v > m || (v == m && ix < mi)) { m = v; mi = ix; }
        }
        rowmax[tid] = m;
        int grow = mb * 128 + tid;
        g_pmax[(size_t)grow * NB + nb] = m;
        g_pidx[(size_t)grow * NB + nb] = nb * 128 + mi;
    }
    __syncthreads();

    // ---- sumexp relative to block-local row max ----
    #pragma unroll
    for (int i = 0; i < 8; i++) {
        float rm = rowmax[ty * 8 + i];
        float ss = 0.f;
        #pragma unroll
        for (int j = 0; j < 8; j++) ss += __expf(acc[i][j] - rm);
        redv[ty * 8 + i][tx] = ss;
    }
    __syncthreads();
    if (tid < 128) {
        float ss = 0.f;
        #pragma unroll
        for (int t = 0; t < 16; t++) ss += redv[tid][t];
        g_psum[(size_t)(mb * 128 + tid) * NB + nb] = ss;
    }
}

// ---------------- kernel 3: merge 64 partials per row ----------------
__global__ void merge_kernel(const int* __restrict__ y) {
    int row  = blockIdx.x * 8 + (threadIdx.x >> 5);
    int lane = threadIdx.x & 31;
    const size_t base = (size_t)row * NB;

    float m = -INFINITY; int mi = 0x7fffffff;
    #pragma unroll
    for (int p = lane; p < NB; p += 32) {
        float v = g_pmax[base + p]; int ix = g_pidx[base + p];
        if (v > m || (v == m && ix < mi)) { m = v; mi = ix; }
    }
    #pragma unroll
    for (int o = 16; o > 0; o >>= 1) {
        float vo = __shfl_down_sync(0xffffffffu, m, o);
        int   io = __shfl_down_sync(0xffffffffu, mi, o);
        if (vo > m || (vo == m && io < mi)) { m = vo; mi = io; }
    }
    m  = __shfl_sync(0xffffffffu, m, 0);
    mi = __shfl_sync(0xffffffffu, mi, 0);

    float tot = 0.f;
    #pragma unroll
    for (int p = lane; p < NB; p += 32)
        tot += g_psum[base + p] * __expf(g_pmax[base + p] - m);
    #pragma unroll
    for (int o = 16; o > 0; o >>= 1) tot += __shfl_down_sync(0xffffffffu, tot, o);

    if (lane == 0) {
        float lse = m + logf(tot);
        g_rloss[row]  = lse - g_sy[row];
        g_rmatch[row] = (mi == y[row]) ? 1.f : 0.f;
    }
}

// ---------------- kernel 4: final means ----------------
__global__ void final_kernel(float* __restrict__ out, int out_size) {
    int t = threadIdx.x;  // 1024 threads
    float ls = g_rloss[t]  + g_rloss[t + 1024];
    float ms = g_rmatch[t] + g_rmatch[t + 1024];
    __shared__ float shl[32], shm[32];
    #pragma unroll
    for (int o = 16; o > 0; o >>= 1) {
        ls += __shfl_down_sync(0xffffffffu, ls, o);
        ms += __shfl_down_sync(0xffffffffu, ms, o);
    }
    if ((t & 31) == 0) { shl[t >> 5] = ls; shm[t >> 5] = ms; }
    __syncthreads();
    if (t < 32) {
        ls = shl[t]; ms = shm[t];
        #pragma unroll
        for (int o = 16; o > 0; o >>= 1) {
            ls += __shfl_down_sync(0xffffffffu, ls, o);
            ms += __shfl_down_sync(0xffffffffu, ms, o);
        }
        if (t == 0) {
            out[0] = ls / (float)BDIM;
            if (out_size > 1) out[1] = ms / (float)BDIM;
        }
    }
}

// ---------------- launch ----------------
extern "C" void kernel_launch(void* const* d_in, const int* in_sizes, int n_in,
                              void* d_out, int out_size) {
    const float* x    = (const float*)d_in[0];
    const int*   y    = (const int*)d_in[1];
    const float* cent = (const float*)d_in[2];
    float* out = (float*)d_out;

    c2_kernel<<<C, 256>>>(cent);
    dim3 grid(NB, BDIM / 128);
    gemm_kernel<<<grid, 256>>>(x, y, cent);
    merge_kernel<<<BDIM / 8, 256>>>(y);
    final_kernel<<<1, 1024>>>(out, out_size);
}

// round 3
// speedup vs baseline: 2.1807x; 2.1807x over previous
#include <cuda_runtime.h>
#include <cuda_bf16.h>
#include <math.h>
#include <stdint.h>

#define BDIM 2048
#define D 1024
#define C 8192
#define KP 3072            // packed K (hi|hi|lo vs hi|lo|hi)
#define NB 64              // 8192 / 128 column blocks
#define NCHUNK 48          // 3072 / 64
#define BK 64              // k elems per chunk (128 bytes)
#define STAGE_BYTES 32768  // A(16KB) + B(16KB)
#define NSTAGE 4

// ---------------- scratch ----------------
__device__ __nv_bfloat16 g_A[(size_t)BDIM * KP];   // [xh | xh | xl]
__device__ __nv_bfloat16 g_B[(size_t)C * KP];      // [ch | cl | ch]
__device__ float g_c2[C];
__device__ float g_pmax[BDIM * NB];
__device__ int   g_pidx[BDIM * NB];
__device__ float g_psum[BDIM * NB];
__device__ float g_sy[BDIM];
__device__ float g_rloss[BDIM];
__device__ float g_rmatch[BDIM];

// ---------------- helpers ----------------
__device__ __forceinline__ uint32_t smem_u32(const void* p) {
    uint32_t a;
    asm("{ .reg .u64 t; cvta.to.shared.u64 t, %1; cvt.u32.u64 %0, t; }" : "=r"(a) : "l"(p));
    return a;
}
#define CP_COMMIT() asm volatile("cp.async.commit_group;" ::: "memory")
#define CP_WAIT(n)  asm volatile("cp.async.wait_group %0;" :: "n"(n) : "memory")

__device__ __forceinline__ void ldsm_x4(uint32_t& r0, uint32_t& r1, uint32_t& r2, uint32_t& r3,
                                        uint32_t addr) {
    asm volatile("ldmatrix.sync.aligned.m8n8.x4.shared.b16 {%0,%1,%2,%3}, [%4];"
                 : "=r"(r0), "=r"(r1), "=r"(r2), "=r"(r3) : "r"(addr));
}
__device__ __forceinline__ void mma_bf16(float* d, uint32_t a0, uint32_t a1, uint32_t a2,
                                         uint32_t a3, uint32_t b0, uint32_t b1) {
    asm volatile(
        "mma.sync.aligned.m16n8k16.row.col.f32.bf16.bf16.f32 "
        "{%0,%1,%2,%3}, {%4,%5,%6,%7}, {%8,%9}, {%0,%1,%2,%3};"
        : "+f"(d[0]), "+f"(d[1]), "+f"(d[2]), "+f"(d[3])
        : "r"(a0), "r"(a1), "r"(a2), "r"(a3), "r"(b0), "r"(b1));
}

// ---------------- prep: split x -> [xh | xh | xl] ----------------
__global__ void split_x_kernel(const float* __restrict__ x) {
    int row = blockIdx.x, t = threadIdx.x;
    float4 v = ((const float4*)(x + (size_t)row * D))[t];
    __nv_bfloat16 h0 = __float2bfloat16(v.x), h1 = __float2bfloat16(v.y);
    __nv_bfloat16 h2 = __float2bfloat16(v.z), h3 = __float2bfloat16(v.w);
    __nv_bfloat16 l0 = __float2bfloat16(v.x - __bfloat162float(h0));
    __nv_bfloat16 l1 = __float2bfloat16(v.y - __bfloat162float(h1));
    __nv_bfloat16 l2 = __float2bfloat16(v.z - __bfloat162float(h2));
    __nv_bfloat16 l3 = __float2bfloat16(v.w - __bfloat162float(h3));
    __nv_bfloat162* b = (__nv_bfloat162*)(g_A + (size_t)row * KP + t * 4);
    __nv_bfloat162 ha = __halves2bfloat162(h0, h1), hb = __halves2bfloat162(h2, h3);
    __nv_bfloat162 la = __halves2bfloat162(l0, l1), lb = __halves2bfloat162(l2, l3);
    b[0] = ha; b[1] = hb;
    b[512] = ha; b[513] = hb;
    b[1024] = la; b[1025] = lb;
}

// ---------------- prep: split centroids -> [ch | cl | ch] + c2 ----------------
__global__ void split_c_kernel(const float* __restrict__ cent) {
    int row = blockIdx.x, t = threadIdx.x;
    float4 v = ((const float4*)(cent + (size_t)row * D))[t];
    __nv_bfloat16 h0 = __float2bfloat16(v.x), h1 = __float2bfloat16(v.y);
    __nv_bfloat16 h2 = __float2bfloat16(v.z), h3 = __float2bfloat16(v.w);
    __nv_bfloat16 l0 = __float2bfloat16(v.x - __bfloat162float(h0));
    __nv_bfloat16 l1 = __float2bfloat16(v.y - __bfloat162float(h1));
    __nv_bfloat16 l2 = __float2bfloat16(v.z - __bfloat162float(h2));
    __nv_bfloat16 l3 = __float2bfloat16(v.w - __bfloat162float(h3));
    __nv_bfloat162* b = (__nv_bfloat162*)(g_B + (size_t)row * KP + t * 4);
    __nv_bfloat162 ha = __halves2bfloat162(h0, h1), hb = __halves2bfloat162(h2, h3);
    __nv_bfloat162 la = __halves2bfloat162(l0, l1), lb = __halves2bfloat162(l2, l3);
    b[0] = ha; b[1] = hb;
    b[512] = la; b[513] = lb;
    b[1024] = ha; b[1025] = hb;

    float s = v.x * v.x + v.y * v.y + v.z * v.z + v.w * v.w;
    __shared__ float sh[8];
    #pragma unroll
    for (int o = 16; o > 0; o >>= 1) s += __shfl_down_sync(0xffffffffu, s, o);
    if ((t & 31) == 0) sh[t >> 5] = s;
    __syncthreads();
    if (t < 8) {
        s = sh[t];
        #pragma unroll
        for (int o = 4; o > 0; o >>= 1) s += __shfl_down_sync(0xffu, s, o);
        if (t == 0) g_c2[row] = s;
    }
}

// ---------------- main GEMM: mma.sync bf16, 128x128 tile, 4-stage cp.async ----
// 8 warps in 2(m) x 4(n); warp tile 64x32; per-warp 4x4 m16n8 fragments.
__device__ __forceinline__ void load_chunk(int mb, int nb, int c, uint32_t stage_base, int tid) {
    #pragma unroll
    for (int i = 0; i < 8; i++) {
        int seg_id = tid + (i << 8);          // 0..2047
        int region = seg_id >> 10;            // 0=A, 1=B
        int row = (seg_id >> 3) & 127;
        int seg = seg_id & 7;
        uint32_t dst = stage_base + (region ? 16384u : 0u)
                     + (uint32_t)(row * 128 + ((seg ^ (row & 7)) << 4));
        const __nv_bfloat16* src =
            (region ? g_B + (size_t)(nb * 128 + row) * KP
                    : g_A + (size_t)(mb * 128 + row) * KP) + c * BK + seg * 8;
        asm volatile("cp.async.cg.shared.global [%0], [%1], 16;" :: "r"(dst), "l"(src) : "memory");
    }
}

__global__ __launch_bounds__(256, 1) void gemm_kernel(const int* __restrict__ y) {
    extern __shared__ char dsm[];
    __shared__ float c2s[128];

    const int nb = blockIdx.x;     // 0..63
    const int mb = blockIdx.y;     // 0..15
    const int tid = threadIdx.x;
    const int wid = tid >> 5, lane = tid & 31;
    const int wm = wid >> 2;       // 0..1
    const int wn = wid & 3;        // 0..3
    const uint32_t dbase = smem_u32(dsm);

    if (tid < 128) c2s[tid] = g_c2[nb * 128 + tid];

    float acc[4][4][4];
    #pragma unroll
    for (int i = 0; i < 4; i++)
        #pragma unroll
        for (int j = 0; j < 4; j++)
            #pragma unroll
            for (int e = 0; e < 4; e++) acc[i][j][e] = 0.f;

    // per-lane ldmatrix row indices
    const int a_row = wm * 64 + (lane & 15);           // + mt*16
    const int a_hi  = lane >> 4;                       // k-half
    const int b_row = wn * 32 + (lane & 7) + ((lane >> 3) & 1) * 8;  // + nt2*16
    const int b_hi  = lane >> 4;

    // prologue: chunks 0..2
    #pragma unroll
    for (int p = 0; p < 3; p++) {
        load_chunk(mb, nb, p, dbase + p * STAGE_BYTES, tid);
        CP_COMMIT();
    }

    for (int k = 0; k < NCHUNK; k++) {
        const uint32_t stage = dbase + (k & 3) * STAGE_BYTES;
        if (k + 3 < NCHUNK) {
            load_chunk(mb, nb, k + 3, dbase + ((k + 3) & 3) * STAGE_BYTES, tid);
            CP_COMMIT();
            CP_WAIT(3);
        } else if (k == NCHUNK - 3) CP_WAIT(2);
        else if (k == NCHUNK - 2) CP_WAIT(1);
        else CP_WAIT(0);
        __syncthreads();

        #pragma unroll
        for (int kk = 0; kk < 4; kk++) {
            uint32_t a[4][4], b0[4], b1[4];
            #pragma unroll
            for (int mt = 0; mt < 4; mt++) {
                int row = a_row + mt * 16;
                int seg = (kk * 2 + a_hi) ^ (row & 7);
                ldsm_x4(a[mt][0], a[mt][1], a[mt][2], a[mt][3],
                        stage + (uint32_t)(row * 128 + (seg << 4)));
            }
            #pragma unroll
            for (int nt2 = 0; nt2 < 2; nt2++) {
                int row = b_row + nt2 * 16;
                int seg = (kk * 2 + b_hi) ^ (row & 7);
                uint32_t r0, r1, r2, r3;
                ldsm_x4(r0, r1, r2, r3,
                        stage + 16384u + (uint32_t)(row * 128 + (seg << 4)));
                b0[nt2 * 2] = r0; b1[nt2 * 2] = r2;
                b0[nt2 * 2 + 1] = r1; b1[nt2 * 2 + 1] = r3;
            }
            #pragma unroll
            for (int mt = 0; mt < 4; mt++)
                #pragma unroll
                for (int nt = 0; nt < 4; nt++)
                    mma_bf16(acc[mt][nt], a[mt][0], a[mt][1], a[mt][2], a[mt][3],
                             b0[nt], b1[nt]);
        }
        __syncthreads();
    }

    // ---- epilogue: acc -> smem C block (stride 130 to dodge conflicts) ----
    float* Cs = (float*)dsm;
    #pragma unroll
    for (int mt = 0; mt < 4; mt++) {
        int r0 = wm * 64 + mt * 16 + (lane >> 2);
        #pragma unroll
        for (int nt = 0; nt < 4; nt++) {
            int c0 = wn * 32 + nt * 8 + (lane & 3) * 2;
            *(float2*)&Cs[r0 * 130 + c0]       = make_float2(acc[mt][nt][0], acc[mt][nt][1]);
            *(float2*)&Cs[(r0 + 8) * 130 + c0] = make_float2(acc[mt][nt][2], acc[mt][nt][3]);
        }
    }
    __syncthreads();

    // ---- per-row online softmax partials: 2 threads per row, 64 cols each ----
    {
        int r = tid >> 1, h = tid & 1;
        int row = mb * 128 + r;
        int yv = y[row];
        float m = -INFINITY, ssum = 0.f;
        int mi = 0;
        #pragma unroll 8
        for (int j = 0; j < 64; j++) {
            int lcol = h * 64 + j;
            float sv = fmaf(2.f, Cs[r * 130 + lcol], -c2s[lcol]);
            int col = nb * 128 + lcol;
            if (sv > m) { ssum = ssum * __expf(m - sv) + 1.f; m = sv; mi = col; }
            else ssum += __expf(sv - m);
            if (col == yv) g_sy[row] = sv;
        }
        // combine the two halves (tids 2r, 2r+1)
        float m2 = __shfl_xor_sync(0xffffffffu, m, 1);
        int  mi2 = __shfl_xor_sync(0xffffffffu, mi, 1);
        float s2 = __shfl_xor_sync(0xffffffffu, ssum, 1);
        float M = (m2 > m || (m2 == m && mi2 < mi)) ? m2 : m;
        int  MI = (m2 > m || (m2 == m && mi2 < mi)) ? mi2 : mi;
        float S = ssum * __expf(m - M) + s2 * __expf(m2 - M);
        if (h == 0) {
            g_pmax[(size_t)row * NB + nb] = M;
            g_pidx[(size_t)row * NB + nb] = MI;
            g_psum[(size_t)row * NB + nb] = S;
        }
    }
}

// ---------------- merge 64 partials per row ----------------
__global__ void merge_kernel(const int* __restrict__ y) {
    int row  = blockIdx.x * 8 + (threadIdx.x >> 5);
    int lane = threadIdx.x & 31;
    const size_t base = (size_t)row * NB;

    float m = -INFINITY; int mi = 0x7fffffff;
    #pragma unroll
    for (int p = lane; p < NB; p += 32) {
        float v = g_pmax[base + p]; int ix = g_pidx[base + p];
        if (v > m || (v == m && ix < mi)) { m = v; mi = ix; }
    }
    #pragma unroll
    for (int o = 16; o > 0; o >>= 1) {
        float vo = __shfl_down_sync(0xffffffffu, m, o);
        int   io = __shfl_down_sync(0xffffffffu, mi, o);
        if (vo > m || (vo == m && io < mi)) { m = vo; mi = io; }
    }
    m  = __shfl_sync(0xffffffffu, m, 0);
    mi = __shfl_sync(0xffffffffu, mi, 0);

    float tot = 0.f;
    #pragma unroll
    for (int p = lane; p < NB; p += 32)
        tot += g_psum[base + p] * __expf(g_pmax[base + p] - m);
    #pragma unroll
    for (int o = 16; o > 0; o >>= 1) tot += __shfl_down_sync(0xffffffffu, tot, o);

    if (lane == 0) {
        float lse = m + logf(tot);
        g_rloss[row]  = lse - g_sy[row];
        g_rmatch[row] = (mi == y[row]) ? 1.f : 0.f;
    }
}

// ---------------- final means ----------------
__global__ void final_kernel(float* __restrict__ out, int out_size) {
    int t = threadIdx.x;
    float ls = g_rloss[t]  + g_rloss[t + 1024];
    float ms = g_rmatch[t] + g_rmatch[t + 1024];
    __shared__ float shl[32], shm[32];
    #pragma unroll
    for (int o = 16; o > 0; o >>= 1) {
        ls += __shfl_down_sync(0xffffffffu, ls, o);
        ms += __shfl_down_sync(0xffffffffu, ms, o);
    }
    if ((t & 31) == 0) { shl[t >> 5] = ls; shm[t >> 5] = ms; }
    __syncthreads();
    if (t < 32) {
        ls = shl[t]; ms = shm[t];
        #pragma unroll
        for (int o = 16; o > 0; o >>= 1) {
            ls += __shfl_down_sync(0xffffffffu, ls, o);
            ms += __shfl_down_sync(0xffffffffu, ms, o);
        }
        if (t == 0) {
            out[0] = ls / (float)BDIM;
            if (out_size > 1) out[1] = ms / (float)BDIM;
        }
    }
}

// ---------------- launch ----------------
extern "C" void kernel_launch(void* const* d_in, const int* in_sizes, int n_in,
                              void* d_out, int out_size) {
    const float* x    = (const float*)d_in[0];
    const int*   y    = (const int*)d_in[1];
    const float* cent = (const float*)d_in[2];
    float* out = (float*)d_out;

    cudaFuncSetAttribute(gemm_kernel, cudaFuncAttributeMaxDynamicSharedMemorySize,
                         NSTAGE * STAGE_BYTES);

    split_x_kernel<<<BDIM, 256>>>(x);
    split_c_kernel<<<C, 256>>>(cent);
    gemm_kernel<<<dim3(NB, BDIM / 128), 256, NSTAGE * STAGE_BYTES>>>(y);
    merge_kernel<<<BDIM / 8, 256>>>(y);
    final_kernel<<<1, 1024>>>(out, out_size);
}

// round 4
// speedup vs baseline: 3.0001x; 1.3758x over previous
#include <cuda_runtime.h>
#include <cuda_fp16.h>
#include <math.h>
#include <stdint.h>

#define BDIM 2048
#define D 1024
#define C 8192
#define KPA 2048           // packed A K: [xh | xl]
#define NB 64              // 8192 / 128 column blocks
#define NCHUNK 32          // 2048 / 64
#define BK 64              // k elems per chunk (128 bytes)
#define STAGE_BYTES 32768  // A(16KB) + B(16KB)
#define NSTAGE 4

// ---------------- scratch ----------------
__device__ __half g_A[(size_t)BDIM * KPA];   // [xh | xl]
__device__ __half g_B[(size_t)C * D];        // [ch]
__device__ float g_c2[C];
__device__ float g_pmax[BDIM * NB];
__device__ int   g_pidx[BDIM * NB];
__device__ float g_psum[BDIM * NB];
__device__ float g_sy[BDIM];
__device__ float g_rloss[BDIM];
__device__ float g_rmatch[BDIM];

// ---------------- helpers ----------------
__device__ __forceinline__ uint32_t smem_u32(const void* p) {
    uint32_t a;
    asm("{ .reg .u64 t; cvta.to.shared.u64 t, %1; cvt.u32.u64 %0, t; }" : "=r"(a) : "l"(p));
    return a;
}
#define CP_COMMIT() asm volatile("cp.async.commit_group;" ::: "memory")
#define CP_WAIT(n)  asm volatile("cp.async.wait_group %0;" :: "n"(n) : "memory")

__device__ __forceinline__ void ldsm_x4(uint32_t& r0, uint32_t& r1, uint32_t& r2, uint32_t& r3,
                                        uint32_t addr) {
    asm volatile("ldmatrix.sync.aligned.m8n8.x4.shared.b16 {%0,%1,%2,%3}, [%4];"
                 : "=r"(r0), "=r"(r1), "=r"(r2), "=r"(r3) : "r"(addr));
}
__device__ __forceinline__ void mma_f16(float* d, uint32_t a0, uint32_t a1, uint32_t a2,
                                        uint32_t a3, uint32_t b0, uint32_t b1) {
    asm volatile(
        "mma.sync.aligned.m16n8k16.row.col.f32.f16.f16.f32 "
        "{%0,%1,%2,%3}, {%4,%5,%6,%7}, {%8,%9}, {%0,%1,%2,%3};"
        : "+f"(d[0]), "+f"(d[1]), "+f"(d[2]), "+f"(d[3])
        : "r"(a0), "r"(a1), "r"(a2), "r"(a3), "r"(b0), "r"(b1));
}

// ---------------- prep: split x -> [xh | xl] fp16 ----------------
__global__ void split_x_kernel(const float* __restrict__ x) {
    int row = blockIdx.x, t = threadIdx.x;
    float4 v = ((const float4*)(x + (size_t)row * D))[t];
    __half h0 = __float2half(v.x), h1 = __float2half(v.y);
    __half h2 = __float2half(v.z), h3 = __float2half(v.w);
    __half l0 = __float2half(v.x - __half2float(h0));
    __half l1 = __float2half(v.y - __half2float(h1));
    __half l2 = __float2half(v.z - __half2float(h2));
    __half l3 = __float2half(v.w - __half2float(h3));
    __half2* b = (__half2*)(g_A + (size_t)row * KPA + t * 4);
    b[0] = __halves2half2(h0, h1); b[1] = __halves2half2(h2, h3);
    b[512] = __halves2half2(l0, l1); b[513] = __halves2half2(l2, l3);  // +1024 elems
}

// ---------------- prep: centroids -> ch fp16 + exact f32 c2 ----------------
__global__ void split_c_kernel(const float* __restrict__ cent) {
    int row = blockIdx.x, t = threadIdx.x;
    float4 v = ((const float4*)(cent + (size_t)row * D))[t];
    __half2* b = (__half2*)(g_B + (size_t)row * D + t * 4);
    b[0] = __halves2half2(__float2half(v.x), __float2half(v.y));
    b[1] = __halves2half2(__float2half(v.z), __float2half(v.w));

    float s = v.x * v.x + v.y * v.y + v.z * v.z + v.w * v.w;
    __shared__ float sh[8];
    #pragma unroll
    for (int o = 16; o > 0; o >>= 1) s += __shfl_down_sync(0xffffffffu, s, o);
    if ((t & 31) == 0) sh[t >> 5] = s;
    __syncthreads();
    if (t < 8) {
        s = sh[t];
        #pragma unroll
        for (int o = 4; o > 0; o >>= 1) s += __shfl_down_sync(0xffu, s, o);
        if (t == 0) g_c2[row] = s;
    }
}

// ---------------- main GEMM: mma.sync fp16, 128x128 tile, 4-stage cp.async ----
// 8 warps in 2(m) x 4(n); warp tile 64x32; per-warp 4x4 m16n8 fragments.
// A K-index = chunk c (0..31); B K-index = c & 15 (B reused for hi and lo halves).
__device__ __forceinline__ void load_chunk(int mb, int nb, int c, uint32_t stage_base, int tid) {
    #pragma unroll
    for (int i = 0; i < 8; i++) {
        int seg_id = tid + (i << 8);          // 0..2047
        int region = seg_id >> 10;            // 0=A, 1=B
        int row = (seg_id >> 3) & 127;
        int seg = seg_id & 7;
        uint32_t dst = stage_base + (region ? 16384u : 0u)
                     + (uint32_t)(row * 128 + ((seg ^ (row & 7)) << 4));
        const __half* src =
            (region ? g_B + (size_t)(nb * 128 + row) * D   + (c & 15) * BK
                    : g_A + (size_t)(mb * 128 + row) * KPA + c * BK) + seg * 8;
        asm volatile("cp.async.cg.shared.global [%0], [%1], 16;" :: "r"(dst), "l"(src) : "memory");
    }
}

__global__ __launch_bounds__(256, 1) void gemm_kernel(const int* __restrict__ y) {
    extern __shared__ char dsm[];
    __shared__ float c2s[128];

    const int nb = blockIdx.x;     // 0..63
    const int mb = blockIdx.y;     // 0..15
    const int tid = threadIdx.x;
    const int wid = tid >> 5, lane = tid & 31;
    const int wm = wid >> 2;       // 0..1
    const int wn = wid & 3;        // 0..3
    const uint32_t dbase = smem_u32(dsm);

    if (tid < 128) c2s[tid] = g_c2[nb * 128 + tid];

    float acc[4][4][4];
    #pragma unroll
    for (int i = 0; i < 4; i++)
        #pragma unroll
        for (int j = 0; j < 4; j++)
            #pragma unroll
            for (int e = 0; e < 4; e++) acc[i][j][e] = 0.f;

    const int a_row = wm * 64 + (lane & 15);
    const int a_hi  = lane >> 4;
    const int b_row = wn * 32 + (lane & 7) + ((lane >> 3) & 1) * 8;
    const int b_hi  = lane >> 4;

    // prologue: chunks 0..2
    #pragma unroll
    for (int p = 0; p < 3; p++) {
        load_chunk(mb, nb, p, dbase + p * STAGE_BYTES, tid);
        CP_COMMIT();
    }

    for (int k = 0; k < NCHUNK; k++) {
        const uint32_t stage = dbase + (k & 3) * STAGE_BYTES;
        if (k < NCHUNK - 2) CP_WAIT(2);
        else if (k == NCHUNK - 2) CP_WAIT(1);
        else CP_WAIT(0);
        __syncthreads();   // single sync per iter: also protects stage reuse below

        #pragma unroll
        for (int kk = 0; kk < 4; kk++) {
            uint32_t a[4][4], b0[4], b1[4];
            #pragma unroll
            for (int mt = 0; mt < 4; mt++) {
                int row = a_row + mt * 16;
                int seg = (kk * 2 + a_hi) ^ (row & 7);
                ldsm_x4(a[mt][0], a[mt][1], a[mt][2], a[mt][3],
                        stage + (uint32_t)(row * 128 + (seg << 4)));
            }
            #pragma unroll
            for (int nt2 = 0; nt2 < 2; nt2++) {
                int row = b_row + nt2 * 16;
                int seg = (kk * 2 + b_hi) ^ (row & 7);
                uint32_t r0, r1, r2, r3;
                ldsm_x4(r0, r1, r2, r3,
                        stage + 16384u + (uint32_t)(row * 128 + (seg << 4)));
                b0[nt2 * 2] = r0; b1[nt2 * 2] = r2;
                b0[nt2 * 2 + 1] = r1; b1[nt2 * 2 + 1] = r3;
            }
            #pragma unroll
            for (int mt = 0; mt < 4; mt++)
                #pragma unroll
                for (int nt = 0; nt < 4; nt++)
                    mma_f16(acc[mt][nt], a[mt][0], a[mt][1], a[mt][2], a[mt][3],
                            b0[nt], b1[nt]);
        }

        if (k + 3 < NCHUNK) {
            load_chunk(mb, nb, k + 3, dbase + ((k + 3) & 3) * STAGE_BYTES, tid);
            CP_COMMIT();
        }
    }
    __syncthreads();

    // ---- epilogue: acc -> smem C block (stride 130 to dodge conflicts) ----
    float* Cs = (float*)dsm;
    #pragma unroll
    for (int mt = 0; mt < 4; mt++) {
        int r0 = wm * 64 + mt * 16 + (lane >> 2);
        #pragma unroll
        for (int nt = 0; nt < 4; nt++) {
            int c0 = wn * 32 + nt * 8 + (lane & 3) * 2;
            *(float2*)&Cs[r0 * 130 + c0]       = make_float2(acc[mt][nt][0], acc[mt][nt][1]);
            *(float2*)&Cs[(r0 + 8) * 130 + c0] = make_float2(acc[mt][nt][2], acc[mt][nt][3]);
        }
    }
    __syncthreads();

    // ---- per-row online softmax partials: 2 threads per row, 64 cols each ----
    {
        int r = tid >> 1, h = tid & 1;
        int row = mb * 128 + r;
        int yv = y[row];
        float m = -INFINITY, ssum = 0.f;
        int mi = 0;
        #pragma unroll 8
        for (int j = 0; j < 64; j++) {
            int lcol = h * 64 + j;
            float sv = fmaf(2.f, Cs[r * 130 + lcol], -c2s[lcol]);
            int col = nb * 128 + lcol;
            if (sv > m) { ssum = ssum * __expf(m - sv) + 1.f; m = sv; mi = col; }
            else ssum += __expf(sv - m);
            if (col == yv) g_sy[row] = sv;
        }
        float m2 = __shfl_xor_sync(0xffffffffu, m, 1);
        int  mi2 = __shfl_xor_sync(0xffffffffu, mi, 1);
        float s2 = __shfl_xor_sync(0xffffffffu, ssum, 1);
        float M = (m2 > m || (m2 == m && mi2 < mi)) ? m2 : m;
        int  MI = (m2 > m || (m2 == m && mi2 < mi)) ? mi2 : mi;
        float S = ssum * __expf(m - M) + s2 * __expf(m2 - M);
        if (h == 0) {
            g_pmax[(size_t)row * NB + nb] = M;
            g_pidx[(size_t)row * NB + nb] = MI;
            g_psum[(size_t)row * NB + nb] = S;
        }
    }
}

// ---------------- merge 64 partials per row ----------------
__global__ void merge_kernel(const int* __restrict__ y) {
    int row  = blockIdx.x * 8 + (threadIdx.x >> 5);
    int lane = threadIdx.x & 31;
    const size_t base = (size_t)row * NB;

    float m = -INFINITY; int mi = 0x7fffffff;
    #pragma unroll
    for (int p = lane; p < NB; p += 32) {
        float v = g_pmax[base + p]; int ix = g_pidx[base + p];
        if (v > m || (v == m && ix < mi)) { m = v; mi = ix; }
    }
    #pragma unroll
    for (int o = 16; o > 0; o >>= 1) {
        float vo = __shfl_down_sync(0xffffffffu, m, o);
        int   io = __shfl_down_sync(0xffffffffu, mi, o);
        if (vo > m || (vo == m && io < mi)) { m = vo; mi = io; }
    }
    m  = __shfl_sync(0xffffffffu, m, 0);
    mi = __shfl_sync(0xffffffffu, mi, 0);

    float tot = 0.f;
    #pragma unroll
    for (int p = lane; p < NB; p += 32)
        tot += g_psum[base + p] * __expf(g_pmax[base + p] - m);
    #pragma unroll
    for (int o = 16; o > 0; o >>= 1) tot += __shfl_down_sync(0xffffffffu, tot, o);

    if (lane == 0) {
        float lse = m + logf(tot);
        g_rloss[row]  = lse - g_sy[row];
        g_rmatch[row] = (mi == y[row]) ? 1.f : 0.f;
    }
}

// ---------------- final means ----------------
__global__ void final_kernel(float* __restrict__ out, int out_size) {
    int t = threadIdx.x;
    float ls = g_rloss[t]  + g_rloss[t + 1024];
    float ms = g_rmatch[t] + g_rmatch[t + 1024];
    __shared__ float shl[32], shm[32];
    #pragma unroll
    for (int o = 16; o > 0; o >>= 1) {
        ls += __shfl_down_sync(0xffffffffu, ls, o);
        ms += __shfl_down_sync(0xffffffffu, ms, o);
    }
    if ((t & 31) == 0) { shl[t >> 5] = ls; shm[t >> 5] = ms; }
    __syncthreads();
    if (t < 32) {
        ls = shl[t]; ms = shm[t];
        #pragma unroll
        for (int o = 16; o > 0; o >>= 1) {
            ls += __shfl_down_sync(0xffffffffu, ls, o);
            ms += __shfl_down_sync(0xffffffffu, ms, o);
        }
        if (t == 0) {
            out[0] = ls / (float)BDIM;
            if (out_size > 1) out[1] = ms / (float)BDIM;
        }
    }
}

// ---------------- launch ----------------
extern "C" void kernel_launch(void* const* d_in, const int* in_sizes, int n_in,
                              void* d_out, int out_size) {
    const float* x    = (const float*)d_in[0];
    const int*   y    = (const int*)d_in[1];
    const float* cent = (const float*)d_in[2];
    float* out = (float*)d_out;

    cudaFuncSetAttribute(gemm_kernel, cudaFuncAttributeMaxDynamicSharedMemorySize,
                         NSTAGE * STAGE_BYTES);

    split_x_kernel<<<BDIM, 256>>>(x);
    split_c_kernel<<<C, 256>>>(cent);
    gemm_kernel<<<dim3(NB, BDIM / 128), 256, NSTAGE * STAGE_BYTES>>>(y);
    merge_kernel<<<BDIM / 8, 256>>>(y);
    final_kernel<<<1, 1024>>>(out, out_size);
}

// round 5
// speedup vs baseline: 4.9608x; 1.6535x over previous
#include <cuda_runtime.h>
#include <cuda_fp16.h>
#include <math.h>
#include <stdint.h>

#define BDIM 2048
#define D 1024
#define C 8192
#define NB 64              // 8192 / 128 column blocks
#define NCHUNK 16          // 1024 / 64
#define BK 64              // k elems per chunk (128 bytes)
#define STAGE_BYTES 32768  // A(16KB) + B(16KB)
#define NSTAGE 4

// ---------------- scratch ----------------
__device__ __half g_A[(size_t)BDIM * D];     // xh
__device__ __half g_B[(size_t)C * D];        // ch
__device__ float g_c2[C];
__device__ float g_pmax[BDIM * NB];
__device__ int   g_pidx[BDIM * NB];
__device__ float g_psum[BDIM * NB];
__device__ float g_sy[BDIM];
__device__ float g_rloss[BDIM];
__device__ float g_rmatch[BDIM];

// ---------------- helpers ----------------
__device__ __forceinline__ uint32_t smem_u32(const void* p) {
    uint32_t a;
    asm("{ .reg .u64 t; cvta.to.shared.u64 t, %1; cvt.u32.u64 %0, t; }" : "=r"(a) : "l"(p));
    return a;
}
#define CP_COMMIT() asm volatile("cp.async.commit_group;" ::: "memory")
#define CP_WAIT(n)  asm volatile("cp.async.wait_group %0;" :: "n"(n) : "memory")

__device__ __forceinline__ void ldsm_x4(uint32_t& r0, uint32_t& r1, uint32_t& r2, uint32_t& r3,
                                        uint32_t addr) {
    asm volatile("ldmatrix.sync.aligned.m8n8.x4.shared.b16 {%0,%1,%2,%3}, [%4];"
                 : "=r"(r0), "=r"(r1), "=r"(r2), "=r"(r3) : "r"(addr));
}
__device__ __forceinline__ void mma_f16(float* d, uint32_t a0, uint32_t a1, uint32_t a2,
                                        uint32_t a3, uint32_t b0, uint32_t b1) {
    asm volatile(
        "mma.sync.aligned.m16n8k16.row.col.f32.f16.f16.f32 "
        "{%0,%1,%2,%3}, {%4,%5,%6,%7}, {%8,%9}, {%0,%1,%2,%3};"
        : "+f"(d[0]), "+f"(d[1]), "+f"(d[2]), "+f"(d[3])
        : "r"(a0), "r"(a1), "r"(a2), "r"(a3), "r"(b0), "r"(b1));
}

// ---------------- prep: x -> fp16 ----------------
__global__ void split_x_kernel(const float* __restrict__ x) {
    int row = blockIdx.x, t = threadIdx.x;
    float4 v = ((const float4*)(x + (size_t)row * D))[t];
    __half2* b = (__half2*)(g_A + (size_t)row * D + t * 4);
    b[0] = __halves2half2(__float2half(v.x), __float2half(v.y));
    b[1] = __halves2half2(__float2half(v.z), __float2half(v.w));
}

// ---------------- prep: centroids -> fp16 + exact f32 c2 ----------------
__global__ void split_c_kernel(const float* __restrict__ cent) {
    int row = blockIdx.x, t = threadIdx.x;
    float4 v = ((const float4*)(cent + (size_t)row * D))[t];
    __half2* b = (__half2*)(g_B + (size_t)row * D + t * 4);
    b[0] = __halves2half2(__float2half(v.x), __float2half(v.y));
    b[1] = __halves2half2(__float2half(v.z), __float2half(v.w));

    float s = v.x * v.x + v.y * v.y + v.z * v.z + v.w * v.w;
    __shared__ float sh[8];
    #pragma unroll
    for (int o = 16; o > 0; o >>= 1) s += __shfl_down_sync(0xffffffffu, s, o);
    if ((t & 31) == 0) sh[t >> 5] = s;
    __syncthreads();
    if (t < 8) {
        s = sh[t];
        #pragma unroll
        for (int o = 4; o > 0; o >>= 1) s += __shfl_down_sync(0xffu, s, o);
        if (t == 0) g_c2[row] = s;
    }
}

// ---------------- main GEMM: mma.sync fp16, 128x128 tile, 4-stage cp.async ----
__device__ __forceinline__ void load_chunk(int mb, int nb, int c, uint32_t stage_base, int tid) {
    #pragma unroll
    for (int i = 0; i < 8; i++) {
        int seg_id = tid + (i << 8);          // 0..2047
        int region = seg_id >> 10;            // 0=A, 1=B
        int row = (seg_id >> 3) & 127;
        int seg = seg_id & 7;
        uint32_t dst = stage_base + (region ? 16384u : 0u)
                     + (uint32_t)(row * 128 + ((seg ^ (row & 7)) << 4));
        const __half* src =
            (region ? g_B + (size_t)(nb * 128 + row) * D
                    : g_A + (size_t)(mb * 128 + row) * D) + c * BK + seg * 8;
        asm volatile("cp.async.cg.shared.global [%0], [%1], 16;" :: "r"(dst), "l"(src) : "memory");
    }
}

__global__ __launch_bounds__(256, 1) void gemm_kernel(const int* __restrict__ y) {
    extern __shared__ char dsm[];
    __shared__ float c2s[128];

    const int nb = blockIdx.x;     // 0..63
    const int mb = blockIdx.y;     // 0..15
    const int tid = threadIdx.x;
    const int wid = tid >> 5, lane = tid & 31;
    const int wm = wid >> 2;       // 0..1
    const int wn = wid & 3;        // 0..3
    const uint32_t dbase = smem_u32(dsm);

    if (tid < 128) c2s[tid] = g_c2[nb * 128 + tid];

    float acc[4][4][4];
    #pragma unroll
    for (int i = 0; i < 4; i++)
        #pragma unroll
        for (int j = 0; j < 4; j++)
            #pragma unroll
            for (int e = 0; e < 4; e++) acc[i][j][e] = 0.f;

    const int a_row = wm * 64 + (lane & 15);
    const int a_hi  = lane >> 4;
    const int b_row = wn * 32 + (lane & 7) + ((lane >> 3) & 1) * 8;
    const int b_hi  = lane >> 4;

    #pragma unroll
    for (int p = 0; p < 3; p++) {
        load_chunk(mb, nb, p, dbase + p * STAGE_BYTES, tid);
        CP_COMMIT();
    }

    for (int k = 0; k < NCHUNK; k++) {
        const uint32_t stage = dbase + (k & 3) * STAGE_BYTES;
        if (k < NCHUNK - 2) CP_WAIT(2);
        else if (k == NCHUNK - 2) CP_WAIT(1);
        else CP_WAIT(0);
        __syncthreads();

        #pragma unroll
        for (int kk = 0; kk < 4; kk++) {
            uint32_t a[4][4], b0[4], b1[4];
            #pragma unroll
            for (int mt = 0; mt < 4; mt++) {
                int row = a_row + mt * 16;
                int seg = (kk * 2 + a_hi) ^ (row & 7);
                ldsm_x4(a[mt][0], a[mt][1], a[mt][2], a[mt][3],
                        stage + (uint32_t)(row * 128 + (seg << 4)));
            }
            #pragma unroll
            for (int nt2 = 0; nt2 < 2; nt2++) {
                int row = b_row + nt2 * 16;
                int seg = (kk * 2 + b_hi) ^ (row & 7);
                uint32_t r0, r1, r2, r3;
                ldsm_x4(r0, r1, r2, r3,
                        stage + 16384u + (uint32_t)(row * 128 + (seg << 4)));
                b0[nt2 * 2] = r0; b1[nt2 * 2] = r2;
                b0[nt2 * 2 + 1] = r1; b1[nt2 * 2 + 1] = r3;
            }
            #pragma unroll
            for (int mt = 0; mt < 4; mt++)
                #pragma unroll
                for (int nt = 0; nt < 4; nt++)
                    mma_f16(acc[mt][nt], a[mt][0], a[mt][1], a[mt][2], a[mt][3],
                            b0[nt], b1[nt]);
        }

        if (k + 3 < NCHUNK) {
            load_chunk(mb, nb, k + 3, dbase + ((k + 3) & 3) * STAGE_BYTES, tid);
            CP_COMMIT();
        }
    }
    __syncthreads();

    // ---- epilogue: acc -> smem C block ----
    float* Cs = (float*)dsm;
    #pragma unroll
    for (int mt = 0; mt < 4; mt++) {
        int r0 = wm * 64 + mt * 16 + (lane >> 2);
        #pragma unroll
        for (int nt = 0; nt < 4; nt++) {
            int c0 = wn * 32 + nt * 8 + (lane & 3) * 2;
            *(float2*)&Cs[r0 * 130 + c0]       = make_float2(acc[mt][nt][0], acc[mt][nt][1]);
            *(float2*)&Cs[(r0 + 8) * 130 + c0] = make_float2(acc[mt][nt][2], acc[mt][nt][3]);
        }
    }
    __syncthreads();

    // ---- per-row online softmax partials: 2 threads per row, 64 cols each ----
    {
        int r = tid >> 1, h = tid & 1;
        int row = mb * 128 + r;
        int yv = y[row];
        float m = -INFINITY, ssum = 0.f;
        int mi = 0;
        #pragma unroll 8
        for (int j = 0; j < 64; j++) {
            int lcol = h * 64 + j;
            float sv = fmaf(2.f, Cs[r * 130 + lcol], -c2s[lcol]);
            int col = nb * 128 + lcol;
            if (sv > m) { ssum = ssum * __expf(m - sv) + 1.f; m = sv; mi = col; }
            else ssum += __expf(sv - m);
            if (col == yv) g_sy[row] = sv;
        }
        float m2 = __shfl_xor_sync(0xffffffffu, m, 1);
        int  mi2 = __shfl_xor_sync(0xffffffffu, mi, 1);
        float s2 = __shfl_xor_sync(0xffffffffu, ssum, 1);
        float M = (m2 > m || (m2 == m && mi2 < mi)) ? m2 : m;
        int  MI = (m2 > m || (m2 == m && mi2 < mi)) ? mi2 : mi;
        float S = ssum * __expf(m - M) + s2 * __expf(m2 - M);
        if (h == 0) {
            g_pmax[(size_t)row * NB + nb] = M;
            g_pidx[(size_t)row * NB + nb] = MI;
            g_psum[(size_t)row * NB + nb] = S;
        }
    }
}

// ---------------- merge 64 partials per row ----------------
__global__ void merge_kernel(const int* __restrict__ y) {
    int row  = blockIdx.x * 8 + (threadIdx.x >> 5);
    int lane = threadIdx.x & 31;
    const size_t base = (size_t)row * NB;

    float m = -INFINITY; int mi = 0x7fffffff;
    #pragma unroll
    for (int p = lane; p < NB; p += 32) {
        float v = g_pmax[base + p]; int ix = g_pidx[base + p];
        if (v > m || (v == m && ix < mi)) { m = v; mi = ix; }
    }
    #pragma unroll
    for (int o = 16; o > 0; o >>= 1) {
        float vo = __shfl_down_sync(0xffffffffu, m, o);
        int   io = __shfl_down_sync(0xffffffffu, mi, o);
        if (vo > m || (vo == m && io < mi)) { m = vo; mi = io; }
    }
    m  = __shfl_sync(0xffffffffu, m, 0);
    mi = __shfl_sync(0xffffffffu, mi, 0);

    float tot = 0.f;
    #pragma unroll
    for (int p = lane; p < NB; p += 32)
        tot += g_psum[base + p] * __expf(g_pmax[base + p] - m);
    #pragma unroll
    for (int o = 16; o > 0; o >>= 1) tot += __shfl_down_sync(0xffffffffu, tot, o);

    if (lane == 0) {
        float lse = m + logf(tot);
        g_rloss[row]  = lse - g_sy[row];
        g_rmatch[row] = (mi == y[row]) ? 1.f : 0.f;
    }
}

// ---------------- final means ----------------
__global__ void final_kernel(float* __restrict__ out, int out_size) {
    int t = threadIdx.x;
    float ls = g_rloss[t]  + g_rloss[t + 1024];
    float ms = g_rmatch[t] + g_rmatch[t + 1024];
    __shared__ float shl[32], shm[32];
    #pragma unroll
    for (int o = 16; o > 0; o >>= 1) {
        ls += __shfl_down_sync(0xffffffffu, ls, o);
        ms += __shfl_down_sync(0xffffffffu, ms, o);
    }
    if ((t & 31) == 0) { shl[t >> 5] = ls; shm[t >> 5] = ms; }
    __syncthreads();
    if (t < 32) {
        ls = shl[t]; ms = shm[t];
        #pragma unroll
        for (int o = 16; o > 0; o >>= 1) {
            ls += __shfl_down_sync(0xffffffffu, ls, o);
            ms += __shfl_down_sync(0xffffffffu, ms, o);
        }
        if (t == 0) {
            out[0] = ls / (float)BDIM;
            if (out_size > 1) out[1] = ms / (float)BDIM;
        }
    }
}

// ---------------- launch ----------------
extern "C" void kernel_launch(void* const* d_in, const int* in_sizes, int n_in,
                              void* d_out, int out_size) {
    const float* x    = (const float*)d_in[0];
    const int*   y    = (const int*)d_in[1];
    const float* cent = (const float*)d_in[2];
    float* out = (float*)d_out;

    cudaFuncSetAttribute(gemm_kernel, cudaFuncAttributeMaxDynamicSharedMemorySize,
                         NSTAGE * STAGE_BYTES);

    split_x_kernel<<<BDIM, 256>>>(x);
    split_c_kernel<<<C, 256>>>(cent);
    gemm_kernel<<<dim3(NB, BDIM / 128), 256, NSTAGE * STAGE_BYTES>>>(y);
    merge_kernel<<<BDIM / 8, 256>>>(y);
    final_kernel<<<1, 1024>>>(out, out_size);
}

// round 6
// speedup vs baseline: 6.3143x; 1.2728x over previous
#include <cuda_runtime.h>
#include <cuda_fp16.h>
#include <math.h>
#include <stdint.h>

#define BDIM 2048
#define D 1024
#define C 8192
#define NB 64              // 8192 / 128 column blocks
#define NCHUNK 16          // 1024 / 64
#define BK 64              // k elems per chunk (128 bytes)
#define STAGE_BYTES 32768  // A(16KB) + B(16KB)
#define NSTAGE 3

// ---------------- scratch ----------------
__device__ __half g_A[(size_t)BDIM * D];     // xh
__device__ __half g_B[(size_t)C * D];        // ch
__device__ float g_c2[C];
__device__ float g_pmax[BDIM * NB];
__device__ int   g_pidx[BDIM * NB];
__device__ float g_psum[BDIM * NB];
__device__ float g_sy[BDIM];
__device__ float g_rloss[BDIM];
__device__ float g_rmatch[BDIM];

// ---------------- helpers ----------------
__device__ __forceinline__ uint32_t smem_u32(const void* p) {
    uint32_t a;
    asm("{ .reg .u64 t; cvta.to.shared.u64 t, %1; cvt.u32.u64 %0, t; }" : "=r"(a) : "l"(p));
    return a;
}
#define CP_COMMIT() asm volatile("cp.async.commit_group;" ::: "memory")
#define CP_WAIT(n)  asm volatile("cp.async.wait_group %0;" :: "n"(n) : "memory")

__device__ __forceinline__ void ldsm_x4(uint32_t& r0, uint32_t& r1, uint32_t& r2, uint32_t& r3,
                                        uint32_t addr) {
    asm volatile("ldmatrix.sync.aligned.m8n8.x4.shared.b16 {%0,%1,%2,%3}, [%4];"
                 : "=r"(r0), "=r"(r1), "=r"(r2), "=r"(r3) : "r"(addr));
}
__device__ __forceinline__ void mma_f16(float* d, uint32_t a0, uint32_t a1, uint32_t a2,
                                        uint32_t a3, uint32_t b0, uint32_t b1) {
    asm volatile(
        "mma.sync.aligned.m16n8k16.row.col.f32.f16.f16.f32 "
        "{%0,%1,%2,%3}, {%4,%5,%6,%7}, {%8,%9}, {%0,%1,%2,%3};"
        : "+f"(d[0]), "+f"(d[1]), "+f"(d[2]), "+f"(d[3])
        : "r"(a0), "r"(a1), "r"(a2), "r"(a3), "r"(b0), "r"(b1));
}

// ---------------- fused prep: x/centroids -> fp16, exact f32 c2 ----------------
// blocks 0..BDIM-1: x rows; blocks BDIM..BDIM+C-1: centroid rows (+c2)
__global__ void prep_kernel(const float* __restrict__ x, const float* __restrict__ cent) {
    int b = blockIdx.x, t = threadIdx.x;
    if (b < BDIM) {
        float4 v = ((const float4*)(x + (size_t)b * D))[t];
        __half2* o = (__half2*)(g_A + (size_t)b * D + t * 4);
        o[0] = __halves2half2(__float2half(v.x), __float2half(v.y));
        o[1] = __halves2half2(__float2half(v.z), __float2half(v.w));
        return;
    }
    int row = b - BDIM;
    float4 v = ((const float4*)(cent + (size_t)row * D))[t];
    __half2* o = (__half2*)(g_B + (size_t)row * D + t * 4);
    o[0] = __halves2half2(__float2half(v.x), __float2half(v.y));
    o[1] = __halves2half2(__float2half(v.z), __float2half(v.w));

    float s = v.x * v.x + v.y * v.y + v.z * v.z + v.w * v.w;
    __shared__ float sh[8];
    #pragma unroll
    for (int o2 = 16; o2 > 0; o2 >>= 1) s += __shfl_down_sync(0xffffffffu, s, o2);
    if ((t & 31) == 0) sh[t >> 5] = s;
    __syncthreads();
    if (t < 8) {
        s = sh[t];
        #pragma unroll
        for (int o2 = 4; o2 > 0; o2 >>= 1) s += __shfl_down_sync(0xffu, s, o2);
        if (t == 0) g_c2[row] = s;
    }
}

// ---------------- main GEMM: mma.sync fp16, 128x128 tile, 3-stage, 2 CTA/SM ----
__device__ __forceinline__ void load_chunk(int mb, int nb, int c, uint32_t stage_base, int tid) {
    #pragma unroll
    for (int i = 0; i < 8; i++) {
        int seg_id = tid + (i << 8);          // 0..2047
        int region = seg_id >> 10;            // 0=A, 1=B
        int row = (seg_id >> 3) & 127;
        int seg = seg_id & 7;
        uint32_t dst = stage_base + (region ? 16384u : 0u)
                     + (uint32_t)(row * 128 + ((seg ^ (row & 7)) << 4));
        const __half* src =
            (region ? g_B + (size_t)(nb * 128 + row) * D
                    : g_A + (size_t)(mb * 128 + row) * D) + c * BK + seg * 8;
        asm volatile("cp.async.cg.shared.global [%0], [%1], 16;" :: "r"(dst), "l"(src) : "memory");
    }
}

__global__ __launch_bounds__(256, 2) void gemm_kernel(const int* __restrict__ y) {
    extern __shared__ char dsm[];
    __shared__ float c2s[128];

    const int nb = blockIdx.x;     // 0..63
    const int mb = blockIdx.y;     // 0..15
    const int tid = threadIdx.x;
    const int wid = tid >> 5, lane = tid & 31;
    const int wm = wid >> 2;       // 0..1
    const int wn = wid & 3;        // 0..3
    const uint32_t dbase = smem_u32(dsm);

    if (tid < 128) c2s[tid] = g_c2[nb * 128 + tid];

    float acc[4][4][4];
    #pragma unroll
    for (int i = 0; i < 4; i++)
        #pragma unroll
        for (int j = 0; j < 4; j++)
            #pragma unroll
            for (int e = 0; e < 4; e++) acc[i][j][e] = 0.f;

    const int a_row = wm * 64 + (lane & 15);
    const int a_hi  = lane >> 4;
    const int b_row = wn * 32 + (lane & 7) + ((lane >> 3) & 1) * 8;
    const int b_hi  = lane >> 4;

    #pragma unroll
    for (int p = 0; p < 2; p++) {
        load_chunk(mb, nb, p, dbase + p * STAGE_BYTES, tid);
        CP_COMMIT();
    }

    for (int k = 0; k < NCHUNK; k++) {
        const uint32_t stage = dbase + (k % 3) * STAGE_BYTES;
        if (k < NCHUNK - 1) CP_WAIT(1);
        else CP_WAIT(0);
        __syncthreads();   // protects stage reuse by the load below

        #pragma unroll
        for (int kk = 0; kk < 4; kk++) {
            uint32_t a[4][4], b0[4], b1[4];
            #pragma unroll
            for (int mt = 0; mt < 4; mt++) {
                int row = a_row + mt * 16;
                int seg = (kk * 2 + a_hi) ^ (row & 7);
                ldsm_x4(a[mt][0], a[mt][1], a[mt][2], a[mt][3],
                        stage + (uint32_t)(row * 128 + (seg << 4)));
            }
            #pragma unroll
            for (int nt2 = 0; nt2 < 2; nt2++) {
                int row = b_row + nt2 * 16;
                int seg = (kk * 2 + b_hi) ^ (row & 7);
                uint32_t r0, r1, r2, r3;
                ldsm_x4(r0, r1, r2, r3,
                        stage + 16384u + (uint32_t)(row * 128 + (seg << 4)));
                b0[nt2 * 2] = r0; b1[nt2 * 2] = r2;
                b0[nt2 * 2 + 1] = r1; b1[nt2 * 2 + 1] = r3;
            }
            #pragma unroll
            for (int mt = 0; mt < 4; mt++)
                #pragma unroll
                for (int nt = 0; nt < 4; nt++)
                    mma_f16(acc[mt][nt], a[mt][0], a[mt][1], a[mt][2], a[mt][3],
                            b0[nt], b1[nt]);
        }

        if (k + 2 < NCHUNK) {
            load_chunk(mb, nb, k + 2, dbase + ((k + 2) % 3) * STAGE_BYTES, tid);
            CP_COMMIT();
        }
    }
    __syncthreads();

    // ---- epilogue: acc -> smem C block ----
    float* Cs = (float*)dsm;
    #pragma unroll
    for (int mt = 0; mt < 4; mt++) {
        int r0 = wm * 64 + mt * 16 + (lane >> 2);
        #pragma unroll
        for (int nt = 0; nt < 4; nt++) {
            int c0 = wn * 32 + nt * 8 + (lane & 3) * 2;
            *(float2*)&Cs[r0 * 130 + c0]       = make_float2(acc[mt][nt][0], acc[mt][nt][1]);
            *(float2*)&Cs[(r0 + 8) * 130 + c0] = make_float2(acc[mt][nt][2], acc[mt][nt][3]);
        }
    }
    __syncthreads();

    // ---- per-row online softmax partials: 2 threads per row, 64 cols each ----
    {
        int r = tid >> 1, h = tid & 1;
        int row = mb * 128 + r;
        int yv = y[row];
        float m = -INFINITY, ssum = 0.f;
        int mi = 0;
        #pragma unroll 8
        for (int j = 0; j < 64; j++) {
            int lcol = h * 64 + j;
            float sv = fmaf(2.f, Cs[r * 130 + lcol], -c2s[lcol]);
            int col = nb * 128 + lcol;
            if (sv > m) { ssum = ssum * __expf(m - sv) + 1.f; m = sv; mi = col; }
            else ssum += __expf(sv - m);
            if (col == yv) g_sy[row] = sv;
        }
        float m2 = __shfl_xor_sync(0xffffffffu, m, 1);
        int  mi2 = __shfl_xor_sync(0xffffffffu, mi, 1);
        float s2 = __shfl_xor_sync(0xffffffffu, ssum, 1);
        float M = (m2 > m || (m2 == m && mi2 < mi)) ? m2 : m;
        int  MI = (m2 > m || (m2 == m && mi2 < mi)) ? mi2 : mi;
        float S = ssum * __expf(m - M) + s2 * __expf(m2 - M);
        if (h == 0) {
            g_pmax[(size_t)row * NB + nb] = M;
            g_pidx[(size_t)row * NB + nb] = MI;
            g_psum[(size_t)row * NB + nb] = S;
        }
    }
}

// ---------------- merge 64 partials per row ----------------
__global__ void merge_kernel(const int* __restrict__ y) {
    int row  = blockIdx.x * 8 + (threadIdx.x >> 5);
    int lane = threadIdx.x & 31;
    const size_t base = (size_t)row * NB;

    float m = -INFINITY; int mi = 0x7fffffff;
    #pragma unroll
    for (int p = lane; p < NB; p += 32) {
        float v = g_pmax[base + p]; int ix = g_pidx[base + p];
        if (v > m || (v == m && ix < mi)) { m = v; mi = ix; }
    }
    #pragma unroll
    for (int o = 16; o > 0; o >>= 1) {
        float vo = __shfl_down_sync(0xffffffffu, m, o);
        int   io = __shfl_down_sync(0xffffffffu, mi, o);
        if (vo > m || (vo == m && io < mi)) { m = vo; mi = io; }
    }
    m  = __shfl_sync(0xffffffffu, m, 0);
    mi = __shfl_sync(0xffffffffu, mi, 0);

    float tot = 0.f;
    #pragma unroll
    for (int p = lane; p < NB; p += 32)
        tot += g_psum[base + p] * __expf(g_pmax[base + p] - m);
    #pragma unroll
    for (int o = 16; o > 0; o >>= 1) tot += __shfl_down_sync(0xffffffffu, tot, o);

    if (lane == 0) {
        float lse = m + logf(tot);
        g_rloss[row]  = lse - g_sy[row];
        g_rmatch[row] = (mi == y[row]) ? 1.f : 0.f;
    }
}

// ---------------- final means ----------------
__global__ void final_kernel(float* __restrict__ out, int out_size) {
    int t = threadIdx.x;
    float ls = g_rloss[t]  + g_rloss[t + 1024];
    float ms = g_rmatch[t] + g_rmatch[t + 1024];
    __shared__ float shl[32], shm[32];
    #pragma unroll
    for (int o = 16; o > 0; o >>= 1) {
        ls += __shfl_down_sync(0xffffffffu, ls, o);
        ms += __shfl_down_sync(0xffffffffu, ms, o);
    }
    if ((t & 31) == 0) { shl[t >> 5] = ls; shm[t >> 5] = ms; }
    __syncthreads();
    if (t < 32) {
        ls = shl[t]; ms = shm[t];
        #pragma unroll
        for (int o = 16; o > 0; o >>= 1) {
            ls += __shfl_down_sync(0xffffffffu, ls, o);
            ms += __shfl_down_sync(0xffffffffu, ms, o);
        }
        if (t == 0) {
            out[0] = ls / (float)BDIM;
            if (out_size > 1) out[1] = ms / (float)BDIM;
        }
    }
}

// ---------------- launch ----------------
extern "C" void kernel_launch(void* const* d_in, const int* in_sizes, int n_in,
                              void* d_out, int out_size) {
    const float* x    = (const float*)d_in[0];
    const int*   y    = (const int*)d_in[1];
    const float* cent = (const float*)d_in[2];
    float* out = (float*)d_out;

    cudaFuncSetAttribute(gemm_kernel, cudaFuncAttributeMaxDynamicSharedMemorySize,
                         NSTAGE * STAGE_BYTES);

    prep_kernel<<<BDIM + C, 256>>>(x, cent);
    gemm_kernel<<<dim3(NB, BDIM / 128), 256, NSTAGE * STAGE_BYTES>>>(y);
    merge_kernel<<<BDIM / 8, 256>>>(y);
    final_kernel<<<1, 1024>>>(out, out_size);
}

// round 7
// speedup vs baseline: 6.5070x; 1.0305x over previous
#include <cuda_runtime.h>
#include <cuda_fp16.h>
#include <math.h>
#include <stdint.h>

#define BDIM 2048
#define D 1024
#define C 8192
#define NB 64              // 8192 / 128 column blocks
#define NCHUNK 16          // 1024 / 64
#define BK 64              // k elems per chunk (128 bytes)
#define STAGE_BYTES 32768  // A(16KB) + B(16KB)
#define NSTAGE 3

// ---------------- scratch ----------------
__device__ __half g_A[(size_t)BDIM * D];     // xh
__device__ __half g_B[(size_t)C * D];        // ch
__device__ float g_c2[C];
__device__ float g_pmax[BDIM * NB];
__device__ int   g_pidx[BDIM * NB];
__device__ float g_psum[BDIM * NB];
__device__ float g_sy[BDIM];
__device__ float g_bloss[64];
__device__ float g_bmatch[64];
__device__ int   g_count;   // zero-init; last block resets to 0 (graph-replay safe)

// ---------------- helpers ----------------
__device__ __forceinline__ uint32_t smem_u32(const void* p) {
    uint32_t a;
    asm("{ .reg .u64 t; cvta.to.shared.u64 t, %1; cvt.u32.u64 %0, t; }" : "=r"(a) : "l"(p));
    return a;
}
#define CP_COMMIT() asm volatile("cp.async.commit_group;" ::: "memory")
#define CP_WAIT(n)  asm volatile("cp.async.wait_group %0;" :: "n"(n) : "memory")

__device__ __forceinline__ void ldsm_x4(uint32_t& r0, uint32_t& r1, uint32_t& r2, uint32_t& r3,
                                        uint32_t addr) {
    asm volatile("ldmatrix.sync.aligned.m8n8.x4.shared.b16 {%0,%1,%2,%3}, [%4];"
                 : "=r"(r0), "=r"(r1), "=r"(r2), "=r"(r3) : "r"(addr));
}
__device__ __forceinline__ void mma_f16(float* d, uint32_t a0, uint32_t a1, uint32_t a2,
                                        uint32_t a3, uint32_t b0, uint32_t b1) {
    asm volatile(
        "mma.sync.aligned.m16n8k16.row.col.f32.f16.f16.f32 "
        "{%0,%1,%2,%3}, {%4,%5,%6,%7}, {%8,%9}, {%0,%1,%2,%3};"
        : "+f"(d[0]), "+f"(d[1]), "+f"(d[2]), "+f"(d[3])
        : "r"(a0), "r"(a1), "r"(a2), "r"(a3), "r"(b0), "r"(b1));
}

// ---------------- fused prep: x/centroids -> fp16, exact f32 c2 ----------------
__global__ void prep_kernel(const float* __restrict__ x, const float* __restrict__ cent) {
    int b = blockIdx.x, t = threadIdx.x;
    if (b < BDIM) {
        float4 v = ((const float4*)(x + (size_t)b * D))[t];
        __half2* o = (__half2*)(g_A + (size_t)b * D + t * 4);
        o[0] = __halves2half2(__float2half(v.x), __float2half(v.y));
        o[1] = __halves2half2(__float2half(v.z), __float2half(v.w));
        return;
    }
    int row = b - BDIM;
    float4 v = ((const float4*)(cent + (size_t)row * D))[t];
    __half2* o = (__half2*)(g_B + (size_t)row * D + t * 4);
    o[0] = __halves2half2(__float2half(v.x), __float2half(v.y));
    o[1] = __halves2half2(__float2half(v.z), __float2half(v.w));

    float s = v.x * v.x + v.y * v.y + v.z * v.z + v.w * v.w;
    __shared__ float sh[8];
    #pragma unroll
    for (int o2 = 16; o2 > 0; o2 >>= 1) s += __shfl_down_sync(0xffffffffu, s, o2);
    if ((t & 31) == 0) sh[t >> 5] = s;
    __syncthreads();
    if (t < 8) {
        s = sh[t];
        #pragma unroll
        for (int o2 = 4; o2 > 0; o2 >>= 1) s += __shfl_down_sync(0xffu, s, o2);
        if (t == 0) g_c2[row] = s;
    }
}

// ---------------- main GEMM: mma.sync fp16, 128x128 tile, 3-stage, 2 CTA/SM ----
__device__ __forceinline__ void load_chunk(int mb, int nb, int c, uint32_t stage_base, int tid) {
    #pragma unroll
    for (int i = 0; i < 8; i++) {
        int seg_id = tid + (i << 8);          // 0..2047
        int region = seg_id >> 10;            // 0=A, 1=B
        int row = (seg_id >> 3) & 127;
        int seg = seg_id & 7;
        uint32_t dst = stage_base + (region ? 16384u : 0u)
                     + (uint32_t)(row * 128 + ((seg ^ (row & 7)) << 4));
        const __half* src =
            (region ? g_B + (size_t)(nb * 128 + row) * D
                    : g_A + (size_t)(mb * 128 + row) * D) + c * BK + seg * 8;
        asm volatile("cp.async.cg.shared.global [%0], [%1], 16;" :: "r"(dst), "l"(src) : "memory");
    }
}

__global__ __launch_bounds__(256, 2) void gemm_kernel(const int* __restrict__ y) {
    extern __shared__ char dsm[];
    __shared__ float c2s[128];
    __shared__ int   ybuf[128];

    const int nb = blockIdx.x;     // 0..63
    const int mb = blockIdx.y;     // 0..15
    const int tid = threadIdx.x;
    const int wid = tid >> 5, lane = tid & 31;
    const int wm = wid >> 2;       // 0..1
    const int wn = wid & 3;        // 0..3
    const uint32_t dbase = smem_u32(dsm);

    if (tid < 128) { c2s[tid] = g_c2[nb * 128 + tid]; ybuf[tid] = y[mb * 128 + tid]; }

    float acc[4][4][4];
    #pragma unroll
    for (int i = 0; i < 4; i++)
        #pragma unroll
        for (int j = 0; j < 4; j++)
            #pragma unroll
            for (int e = 0; e < 4; e++) acc[i][j][e] = 0.f;

    const int a_row = wm * 64 + (lane & 15);
    const int a_hi  = lane >> 4;
    const int b_row = wn * 32 + (lane & 7) + ((lane >> 3) & 1) * 8;
    const int b_hi  = lane >> 4;

    #pragma unroll
    for (int p = 0; p < 2; p++) {
        load_chunk(mb, nb, p, dbase + p * STAGE_BYTES, tid);
        CP_COMMIT();
    }

    for (int k = 0; k < NCHUNK; k++) {
        const uint32_t stage = dbase + (k % 3) * STAGE_BYTES;
        if (k < NCHUNK - 1) CP_WAIT(1);
        else CP_WAIT(0);
        __syncthreads();

        #pragma unroll
        for (int kk = 0; kk < 4; kk++) {
            uint32_t a[4][4], b0[4], b1[4];
            #pragma unroll
            for (int mt = 0; mt < 4; mt++) {
                int row = a_row + mt * 16;
                int seg = (kk * 2 + a_hi) ^ (row & 7);
                ldsm_x4(a[mt][0], a[mt][1], a[mt][2], a[mt][3],
                        stage + (uint32_t)(row * 128 + (seg << 4)));
            }
            #pragma unroll
            for (int nt2 = 0; nt2 < 2; nt2++) {
                int row = b_row + nt2 * 16;
                int seg = (kk * 2 + b_hi) ^ (row & 7);
                uint32_t r0, r1, r2, r3;
                ldsm_x4(r0, r1, r2, r3,
                        stage + 16384u + (uint32_t)(row * 128 + (seg << 4)));
                b0[nt2 * 2] = r0; b1[nt2 * 2] = r2;
                b0[nt2 * 2 + 1] = r1; b1[nt2 * 2 + 1] = r3;
            }
            #pragma unroll
            for (int mt = 0; mt < 4; mt++)
                #pragma unroll
                for (int nt = 0; nt < 4; nt++)
                    mma_f16(acc[mt][nt], a[mt][0], a[mt][1], a[mt][2], a[mt][3],
                            b0[nt], b1[nt]);
        }

        if (k + 2 < NCHUNK) {
            load_chunk(mb, nb, k + 2, dbase + ((k + 2) % 3) * STAGE_BYTES, tid);
            CP_COMMIT();
        }
    }
    __syncthreads();   // mainloop smem reads done; dsm now reusable

    // ---- in-register epilogue: online softmax partials from acc fragments ----
    // fragment map: acc[mt][nt][{0,1}] -> row wm*64+mt*16+(lane>>2),    cols +0,+1
    //               acc[mt][nt][{2,3}] -> row wm*64+mt*16+(lane>>2)+8
    float* red_m = (float*)dsm;               // [128][4]
    int*   red_i = (int*)(dsm + 2048);        // [128][4]
    float* red_s = (float*)(dsm + 4096);      // [128][4]

    const int q  = lane >> 2;
    const int c4 = (lane & 3) * 2;
    #pragma unroll
    for (int mt = 0; mt < 4; mt++) {
        #pragma unroll
        for (int h = 0; h < 2; h++) {
            const int r  = wm * 64 + mt * 16 + h * 8 + q;   // local row
            const int yv = ybuf[r];
            float m = -INFINITY, ssum = 0.f; int mi = 0;
            #pragma unroll
            for (int nt = 0; nt < 4; nt++) {
                #pragma unroll
                for (int e = 0; e < 2; e++) {
                    int lcol = wn * 32 + nt * 8 + c4 + e;
                    float sv = fmaf(2.f, acc[mt][nt][h * 2 + e], -c2s[lcol]);
                    int col = nb * 128 + lcol;
                    if (sv > m) { ssum = ssum * __expf(m - sv) + 1.f; m = sv; mi = col; }
                    else ssum += __expf(sv - m);
                    if (col == yv) g_sy[mb * 128 + r] = sv;
                }
            }
            #pragma unroll
            for (int o = 1; o <= 2; o <<= 1) {
                float m2 = __shfl_xor_sync(0xffffffffu, m, o);
                int  mi2 = __shfl_xor_sync(0xffffffffu, mi, o);
                float s2 = __shfl_xor_sync(0xffffffffu, ssum, o);
                bool take = (m2 > m) || (m2 == m && mi2 < mi);
                float M = take ? m2 : m;
                int  MI = take ? mi2 : mi;
                ssum = ssum * __expf(m - M) + s2 * __expf(m2 - M);
                m = M; mi = MI;
            }
            if ((lane & 3) == 0) {
                red_m[r * 4 + wn] = m; red_i[r * 4 + wn] = mi; red_s[r * 4 + wn] = ssum;
            }
        }
    }
    __syncthreads();
    if (tid < 128) {
        float m = -INFINITY, S = 0.f; int mi = 0x7fffffff;
        #pragma unroll
        for (int w = 0; w < 4; w++) {
            float m2 = red_m[tid * 4 + w]; int i2 = red_i[tid * 4 + w]; float s2 = red_s[tid * 4 + w];
            bool take = (m2 > m) || (m2 == m && i2 < mi);
            float M = take ? m2 : m;
            int  MI = take ? i2 : mi;
            S = S * __expf(m - M) + s2 * __expf(m2 - M);
            m = M; mi = MI;
        }
        int row = mb * 128 + tid;
        g_pmax[(size_t)row * NB + nb] = m;
        g_pidx[(size_t)row * NB + nb] = mi;
        g_psum[(size_t)row * NB + nb] = S;
    }
}

// ---------------- fused merge + final: 64 blocks, last block reduces ----------------
__global__ void merge_final_kernel(const int* __restrict__ y, float* __restrict__ out,
                                   int out_size) {
    const int tid = threadIdx.x, bid = blockIdx.x;
    const int rl = tid >> 3;              // local row 0..31
    const int sub = tid & 7;
    const int row = bid * 32 + rl;
    const size_t base = (size_t)row * NB;

    float m = -INFINITY; int mi = 0x7fffffff;
    #pragma unroll
    for (int p = sub; p < NB; p += 8) {
        float v = g_pmax[base + p]; int ix = g_pidx[base + p];
        if (v > m || (v == m && ix < mi)) { m = v; mi = ix; }
    }
    #pragma unroll
    for (int o = 4; o > 0; o >>= 1) {
        float vo = __shfl_down_sync(0xffffffffu, m, o, 8);
        int   io = __shfl_down_sync(0xffffffffu, mi, o, 8);
        if (vo > m || (vo == m && io < mi)) { m = vo; mi = io; }
    }
    m  = __shfl_sync(0xffffffffu, m, 0, 8);
    mi = __shfl_sync(0xffffffffu, mi, 0, 8);

    float tot = 0.f;
    #pragma unroll
    for (int p = sub; p < NB; p += 8)
        tot += g_psum[base + p] * __expf(g_pmax[base + p] - m);
    #pragma unroll
    for (int o = 4; o > 0; o >>= 1) tot += __shfl_down_sync(0xffffffffu, tot, o, 8);

    __shared__ float sl[32], sm_[32];
    if (sub == 0) {
        float lse = m + logf(tot);
        sl[rl]  = lse - g_sy[row];
        sm_[rl] = (mi == y[row]) ? 1.f : 0.f;
    }
    __syncthreads();
    if (tid == 0) {
        float L = 0.f, M = 0.f;
        #pragma unroll
        for (int i = 0; i < 32; i++) { L += sl[i]; M += sm_[i]; }
        g_bloss[bid] = L; g_bmatch[bid] = M;
        __threadfence();
        int old = atomicAdd(&g_count, 1);
        if (old == 63) {
            __threadfence();
            float TL = 0.f, TM = 0.f;
            for (int i = 0; i < 64; i++) { TL += g_bloss[i]; TM += g_bmatch[i]; }
            out[0] = TL / (float)BDIM;
            if (out_size > 1) out[1] = TM / (float)BDIM;
            g_count = 0;   // reset for next graph replay
        }
    }
}

// ---------------- launch ----------------
extern "C" void kernel_launch(void* const* d_in, const int* in_sizes, int n_in,
                              void* d_out, int out_size) {
    const float* x    = (const float*)d_in[0];
    const int*   y    = (const int*)d_in[1];
    const float* cent = (const float*)d_in[2];
    float* out = (float*)d_out;

    cudaFuncSetAttribute(gemm_kernel, cudaFuncAttributeMaxDynamicSharedMemorySize,
                         NSTAGE * STAGE_BYTES);

    prep_kernel<<<BDIM + C, 256>>>(x, cent);
    gemm_kernel<<<dim3(NB, BDIM / 128), 256, NSTAGE * STAGE_BYTES>>>(y);
    merge_final_kernel<<<64, 256>>>(y, out, out_size);
}